// round 14
// baseline (speedup 1.0000x reference)
#include <cuda_runtime.h>
#include <cuda_fp16.h>

#define NN   50000
#define EE   800000
#define INC  128
#define HID  96
#define OUTC 40
#define SLOPE 0.2f

#define SCAN_B 1024
#define SCAN_NB ((NN + SCAN_B - 1) / SCAN_B)

// ---------------- scratch (device globals; no allocation allowed) ----------
__device__ __half g_h1[(size_t)NN * HID];    // fp16 features (gather-only)
__device__ __half g_h2[(size_t)NN * OUTC];
__device__ float  g_agg1[(size_t)NN * HID];  // normalized layer-1 agg (fp32)
__device__ float  g_as1[NN], g_ad1[NN];
__device__ float  g_as2[NN], g_ad2[NN];
__device__ int    g_cnt[NN];                 // zero-init at load; self-restoring
__device__ int    g_off[NN + 1];
__device__ int    g_cur[NN];
__device__ int    g_part[SCAN_NB];
__device__ int    g_csr[EE];

// ---------------- packed f32x2 helpers (sm_100+ PTX) -------------------------
__device__ __forceinline__ unsigned long long pk2(float a) {
    unsigned long long r;
    asm("mov.b64 %0, {%1, %1};" : "=l"(r) : "f"(a));
    return r;
}
__device__ __forceinline__ void ffma2(unsigned long long& d,
                                      unsigned long long a,
                                      unsigned long long b) {
    asm("fma.rn.f32x2 %0, %1, %2, %3;" : "=l"(d) : "l"(a), "l"(b), "l"(d));
}
__device__ __forceinline__ float2 upk2(unsigned long long v) {
    float2 f;
    asm("mov.b64 {%0, %1}, %2;" : "=f"(f.x), "=f"(f.y) : "l"(v));
    return f;
}

// ---------------- CSR build --------------------------------------------------
__global__ void k_hist(const int* __restrict__ ei) {
    int i = blockIdx.x * blockDim.x + threadIdx.x;
    if (i < EE) atomicAdd(&g_cnt[ei[EE + i]], 1);
}

// scan1 also re-zeroes g_cnt after consuming it (invariant: g_cnt==0 at the
// start of every kernel_launch call; zero-init at module load seeds it).
__global__ void k_scan1() {
    __shared__ int sm[SCAN_B];
    int tid = threadIdx.x;
    int g = blockIdx.x * SCAN_B + tid;
    int v = (g < NN) ? g_cnt[g] : 0;
    if (g < NN) g_cnt[g] = 0;
    sm[tid] = v;
    __syncthreads();
#pragma unroll
    for (int ofs = 1; ofs < SCAN_B; ofs <<= 1) {
        int t = (tid >= ofs) ? sm[tid - ofs] : 0;
        __syncthreads();
        sm[tid] += t;
        __syncthreads();
    }
    if (g < NN) g_off[g] = sm[tid] - v;     // exclusive within block
    if (tid == SCAN_B - 1) g_part[blockIdx.x] = sm[tid];
}

// parallel Hillis-Steele over the 49 block partials
__global__ void k_scan2() {
    __shared__ int sm[64];
    int tid = threadIdx.x;
    int v = (tid < SCAN_NB) ? g_part[tid] : 0;
    sm[tid] = v;
    __syncthreads();
#pragma unroll
    for (int o = 1; o < 64; o <<= 1) {
        int t = (tid >= o) ? sm[tid - o] : 0;
        __syncthreads();
        sm[tid] += t;
        __syncthreads();
    }
    if (tid < SCAN_NB) g_part[tid] = sm[tid] - v;   // exclusive
}

__global__ void k_scan3() {
    int g = blockIdx.x * SCAN_B + threadIdx.x;
    if (g < NN) {
        int o = g_off[g] + g_part[blockIdx.x];
        g_off[g] = o;
        g_cur[g] = o;
    }
    if (g == 0) g_off[NN] = EE;
}

__global__ void k_fill(const int* __restrict__ ei) {
    int i = blockIdx.x * blockDim.x + threadIdx.x;
    if (i >= EE) return;
    int d = ei[EE + i];
    int pos = atomicAdd(&g_cur[d], 1);
    g_csr[pos] = ei[i];
}

// ---------------- tiled GEMM (packed f32x2 math) ----------------------------
// H[n,CO] = X[n,K] @ W[K,CO], H stored fp16 (half2 pairs). Epilogue computes
// per-node attention scalars from the fp32 accumulators via smem reduction +
// direct store. Optional fused relu(x + bias) on the X-tile load.
template <int K, int CO, int TM, int TCOLS, int TROWS, bool FUSE>
__global__ void k_gemm_t(const float* __restrict__ X, const float* __restrict__ W,
                         const float* __restrict__ bias,
                         const float* __restrict__ asrc, const float* __restrict__ adst,
                         float* __restrict__ oas, float* __restrict__ oad,
                         __half* __restrict__ H, int n) {
    constexpr int KT = 32;
    constexpr int THREADS = TCOLS * TROWS;
    constexpr int RPT = TM / TROWS;
    __shared__ float Xs[TM][KT];
    __shared__ __align__(16) float Ws[KT][CO];
    __shared__ float Ps[TM][TCOLS];
    __shared__ float Pd[TM][TCOLS];

    const int tid  = threadIdx.x;
    const int tcol = tid % TCOLS;
    const int trow = tid / TCOLS;
    const int row0 = blockIdx.x * TM;

    unsigned long long accA[RPT], accB[RPT];   // cols (4c,4c+1) and (4c+2,4c+3)
#pragma unroll
    for (int i = 0; i < RPT; i++) { accA[i] = 0ull; accB[i] = 0ull; }

    for (int kt = 0; kt < K; kt += KT) {
        for (int idx = tid; idx < TM * (KT / 4); idx += THREADS) {
            int r  = idx / (KT / 4);
            int c4 = idx % (KT / 4);
            int grow = row0 + r;
            float4 v = make_float4(0.f, 0.f, 0.f, 0.f);
            if (grow < n) {
                v = *(const float4*)(X + (size_t)grow * K + kt + c4 * 4);
                if constexpr (FUSE) {
                    const float* bb = bias + kt + c4 * 4;
                    v.x = fmaxf(v.x + bb[0], 0.f);
                    v.y = fmaxf(v.y + bb[1], 0.f);
                    v.z = fmaxf(v.z + bb[2], 0.f);
                    v.w = fmaxf(v.w + bb[3], 0.f);
                }
            }
            *(float4*)&Xs[r][c4 * 4] = v;
        }
        for (int idx = tid; idx < KT * (CO / 4); idx += THREADS) {
            int r  = idx / (CO / 4);
            int c4 = idx % (CO / 4);
            *(float4*)&Ws[r][c4 * 4] =
                *(const float4*)(W + (size_t)(kt + r) * CO + c4 * 4);
        }
        __syncthreads();

#pragma unroll
        for (int k4 = 0; k4 < KT; k4 += 4) {
            float4 xs[RPT];
#pragma unroll
            for (int i = 0; i < RPT; i++)
                xs[i] = *(float4*)&Xs[trow * RPT + i][k4];
#pragma unroll
            for (int kk = 0; kk < 4; kk++) {
                const unsigned long long* wp =
                    (const unsigned long long*)&Ws[k4 + kk][tcol * 4];
                unsigned long long w01 = wp[0];
                unsigned long long w23 = wp[1];
#pragma unroll
                for (int i = 0; i < RPT; i++) {
                    float xv = (kk == 0) ? xs[i].x : (kk == 1) ? xs[i].y
                             : (kk == 2) ? xs[i].z : xs[i].w;
                    unsigned long long xp = pk2(xv);
                    ffma2(accA[i], xp, w01);
                    ffma2(accB[i], xp, w23);
                }
            }
        }
        __syncthreads();
    }

    // ---- epilogue: store H (fp16); attention scalars via smem reduction ----
    float4 vs = *(const float4*)(asrc + tcol * 4);
    float4 vd = *(const float4*)(adst + tcol * 4);
#pragma unroll
    for (int i = 0; i < RPT; i++) {
        int r = trow * RPT + i;
        int grow = row0 + r;
        float2 a01 = upk2(accA[i]);
        float2 a23 = upk2(accB[i]);
        if (grow < n) {
            __half2 h01 = __floats2half2_rn(a01.x, a01.y);
            __half2 h23 = __floats2half2_rn(a23.x, a23.y);
            uint2 pk;
            pk.x = *(unsigned*)&h01;
            pk.y = *(unsigned*)&h23;
            *(uint2*)(H + (size_t)grow * CO + tcol * 4) = pk;
        }
        Ps[r][tcol] = a01.x * vs.x + a01.y * vs.y + a23.x * vs.z + a23.y * vs.w;
        Pd[r][tcol] = a01.x * vd.x + a01.y * vd.y + a23.x * vd.z + a23.y * vd.w;
    }
    __syncthreads();
    for (int r = tid; r < TM; r += THREADS) {
        int grow = row0 + r;
        if (grow < n) {
            float ss = 0.f, sd = 0.f;
#pragma unroll
            for (int c = 0; c < TCOLS; c++) { ss += Ps[r][c]; sd += Pd[r][c]; }
            oas[grow] = ss;
            oad[grow] = sd;
        }
    }
}

// ---------------- CSR gather aggregation: one warp per dst node --------------
// Features are fp16; lane loads ONE half2 (4B) per segment: segment j covers
// half2 indices [32j, 32j+32) of the HU=C/2 per row. (w, src) staged through
// per-warp smem; consume loop unrolled -> coalesced 128B wavefronts.
// out[node] = (w_self*h[node] + sum_e w_e*h[src_e]) / (w_self + sum_e w_e)
// FINAL: fuse bias + log_softmax (lane owns channels 2*idx, 2*idx+1).
template <int C, bool FINAL>
__global__ void k_agg_csr(const __half* __restrict__ h,
                          const float* __restrict__ as,
                          const float* __restrict__ ad,
                          const float* __restrict__ bias,
                          float* __restrict__ aggout) {
    constexpr int HU  = C / 2;                 // half2 words per row
    constexpr int SEG = (HU + 31) / 32;        // segments per row (2 or 1)
    __shared__ float sw[8][32];
    __shared__ int   ssrc[8][32];
    int wid  = threadIdx.x >> 5;
    int node = blockIdx.x * (blockDim.x >> 5) + wid;
    int lane = threadIdx.x & 31;
    if (node >= NN) return;

    const unsigned* hu = (const unsigned*)h;

    float ad_n = ad[node];
    float vself = as[node] + ad_n;
    vself = (vself > 0.f) ? vself : SLOPE * vself;
    float wself = __expf(vself);

    bool act[SEG];
    int  hidx[SEG];
#pragma unroll
    for (int j = 0; j < SEG; j++) {
        hidx[j] = 32 * j + lane;
        act[j]  = hidx[j] < HU;
    }

    float2 acc[SEG];
#pragma unroll
    for (int j = 0; j < SEG; j++) {
        acc[j] = make_float2(0.f, 0.f);
        if (act[j]) {
            unsigned p = hu[(size_t)node * HU + hidx[j]];
            float2 f = __half22float2(*(__half2*)&p);
            acc[j].x = wself * f.x;
            acc[j].y = wself * f.y;
        }
    }

    int beg = g_off[node];
    int end = g_off[node + 1];
    float sloc = 0.f;

    for (int base = beg; base < end; base += 32) {
        int e = base + lane;
        bool valid = e < end;
        int src = valid ? g_csr[e] : 0;
        float w = 0.f;
        if (valid) {
            float v = as[src] + ad_n;
            v = (v > 0.f) ? v : SLOPE * v;
            w = __expf(v);
        }
        sloc += w;
        sw[wid][lane]   = w;
        ssrc[wid][lane] = src;
        __syncwarp();
        int cnt = min(32, end - base);
#pragma unroll 4
        for (int k = 0; k < cnt; k++) {
            float wk = sw[wid][k];
            const unsigned* hr = hu + (size_t)ssrc[wid][k] * HU;
#pragma unroll
            for (int j = 0; j < SEG; j++) {
                if (act[j]) {
                    unsigned p = hr[hidx[j]];
                    float2 f = __half22float2(*(__half2*)&p);
                    acc[j].x += wk * f.x;
                    acc[j].y += wk * f.y;
                }
            }
        }
        __syncwarp();
    }

#pragma unroll
    for (int o = 16; o; o >>= 1) sloc += __shfl_xor_sync(0xffffffffu, sloc, o);
    float inv = 1.f / (sloc + wself);

    if constexpr (!FINAL) {
#pragma unroll
        for (int j = 0; j < SEG; j++) {
            if (act[j]) {
                float2 r = make_float2(acc[j].x * inv, acc[j].y * inv);
                *(float2*)(aggout + (size_t)node * C + 2 * hidx[j]) = r;
            }
        }
    } else {
        // lane owns channels (2*hidx, 2*hidx+1) per active segment
        float2 z[SEG];
        float mx = -3.4e38f;
#pragma unroll
        for (int j = 0; j < SEG; j++) {
            if (act[j]) {
                z[j].x = acc[j].x * inv + bias[2 * hidx[j]];
                z[j].y = acc[j].y * inv + bias[2 * hidx[j] + 1];
                mx = fmaxf(mx, fmaxf(z[j].x, z[j].y));
            }
        }
#pragma unroll
        for (int o = 16; o; o >>= 1) mx = fmaxf(mx, __shfl_xor_sync(0xffffffffu, mx, o));
        float sm = 0.f;
#pragma unroll
        for (int j = 0; j < SEG; j++) {
            if (act[j]) sm += __expf(z[j].x - mx) + __expf(z[j].y - mx);
        }
#pragma unroll
        for (int o = 16; o; o >>= 1) sm += __shfl_xor_sync(0xffffffffu, sm, o);
        float lse = mx + __logf(sm);
#pragma unroll
        for (int j = 0; j < SEG; j++) {
            if (act[j]) {
                float2 r = make_float2(z[j].x - lse, z[j].y - lse);
                *(float2*)(aggout + (size_t)node * C + 2 * hidx[j]) = r;
            }
        }
    }
}

// ---------------- launch -----------------------------------------------------
static inline int cdiv(long long a, int b) { return (int)((a + b - 1) / b); }

extern "C" void kernel_launch(void* const* d_in, const int* in_sizes, int n_in,
                              void* d_out, int out_size) {
    const float* x    = (const float*)d_in[0];
    const int*   ei   = (const int*)d_in[1];   // int32 (JAX x64 disabled)
    // d_in[2] = new_edge_indexs — unused by the reference
    const float* W1   = (const float*)d_in[3];
    const float* asr1 = (const float*)d_in[4];
    const float* ads1 = (const float*)d_in[5];
    const float* b1   = (const float*)d_in[6];
    const float* W2   = (const float*)d_in[7];
    const float* asr2 = (const float*)d_in[8];
    const float* ads2 = (const float*)d_in[9];
    const float* b2   = (const float*)d_in[10];
    float* out = (float*)d_out;

    __half *h1, *h2;
    float *agg1, *as1, *ad1, *as2, *ad2;
    cudaGetSymbolAddress((void**)&h1, g_h1);
    cudaGetSymbolAddress((void**)&h2, g_h2);
    cudaGetSymbolAddress((void**)&agg1, g_agg1);
    cudaGetSymbolAddress((void**)&as1, g_as1);
    cudaGetSymbolAddress((void**)&ad1, g_ad1);
    cudaGetSymbolAddress((void**)&as2, g_as2);
    cudaGetSymbolAddress((void**)&ad2, g_ad2);

    // one-time side stream + events (host resources only; identical GPU work
    // per call, captured via the standard fork/join event pattern)
    static cudaStream_t s2 = nullptr;
    static cudaEvent_t evFork = nullptr, evJoin = nullptr;
    if (!s2) {
        cudaStreamCreateWithFlags(&s2, cudaStreamNonBlocking);
        cudaEventCreateWithFlags(&evFork, cudaEventDisableTiming);
        cudaEventCreateWithFlags(&evJoin, cudaEventDisableTiming);
    }

    const int T = 256;

    // ---- fork immediately: CSR build runs beside GEMM1 ----------------------
    cudaEventRecord(evFork, 0);
    cudaStreamWaitEvent(s2, evFork, 0);

    // side stream: CSR build (g_cnt is zero by invariant; scan1 re-zeroes it)
    k_hist<<<cdiv(EE, T), T, 0, s2>>>(ei);
    k_scan1<<<SCAN_NB, SCAN_B, 0, s2>>>();
    k_scan2<<<1, 64, 0, s2>>>();
    k_scan3<<<SCAN_NB, SCAN_B, 0, s2>>>();
    k_fill<<<cdiv(EE, T), T, 0, s2>>>(ei);
    cudaEventRecord(evJoin, s2);

    // main stream: GEMM1 starts at t=0 (384 thr, RPT=4)
    k_gemm_t<INC, HID, 64, 24, 16, false>
        <<<cdiv(NN, 64), 24 * 16>>>(x, W1, nullptr, asr1, ads1, as1, ad1, h1, NN);

    // join: aggregation needs both GEMM1 (main) and CSR (s2)
    cudaStreamWaitEvent(0, evJoin, 0);
    k_agg_csr<HID, false><<<cdiv(NN, 8), 256>>>(h1, as1, ad1, nullptr, agg1);

    // ---- layer 2 ----
    k_gemm_t<HID, OUTC, 128, 10, 16, true>
        <<<cdiv(NN, 128), 10 * 16>>>(agg1, W2, b1, asr2, ads2, as2, ad2, h2, NN);
    k_agg_csr<OUTC, true><<<cdiv(NN, 8), 256>>>(h2, as2, ad2, b2, out);
}

// round 15
// speedup vs baseline: 1.0570x; 1.0570x over previous
#include <cuda_runtime.h>

#define NN   50000
#define EE   800000
#define INC  128
#define HID  96
#define OUTC 40
#define SLOPE 0.2f

#define SCAN_B 1024
#define SCAN_NB ((NN + SCAN_B - 1) / SCAN_B)

// ---------------- scratch (device globals; no allocation allowed) ----------
__device__ float g_h1[(size_t)NN * HID];
__device__ float g_h2[(size_t)NN * OUTC];
__device__ float g_agg1[(size_t)NN * HID];   // normalized layer-1 aggregation
__device__ float g_as1[NN], g_ad1[NN];
__device__ float g_as2[NN], g_ad2[NN];
__device__ int   g_cnt[NN];                  // zero at load; scan1 self-restores
__device__ int   g_off[NN + 1];
__device__ int   g_cur[NN];
__device__ int   g_part[SCAN_NB];
__device__ int   g_csr[EE];

// ---------------- packed f32x2 helpers (sm_100+ PTX) -------------------------
__device__ __forceinline__ unsigned long long pk2(float a) {
    unsigned long long r;
    asm("mov.b64 %0, {%1, %1};" : "=l"(r) : "f"(a));
    return r;
}
__device__ __forceinline__ void ffma2(unsigned long long& d,
                                      unsigned long long a,
                                      unsigned long long b) {
    asm("fma.rn.f32x2 %0, %1, %2, %3;" : "=l"(d) : "l"(a), "l"(b), "l"(d));
}
__device__ __forceinline__ float2 upk2(unsigned long long v) {
    float2 f;
    asm("mov.b64 {%0, %1}, %2;" : "=f"(f.x), "=f"(f.y) : "l"(v));
    return f;
}

// ---------------- CSR build --------------------------------------------------
// int2-vectorized histogram: 2 edges per thread
__global__ void k_hist(const int* __restrict__ ei) {
    int i = blockIdx.x * blockDim.x + threadIdx.x;
    if (i < EE / 2) {
        int2 d = ((const int2*)(ei + EE))[i];
        atomicAdd(&g_cnt[d.x], 1);
        atomicAdd(&g_cnt[d.y], 1);
    }
}

// scan1 also re-zeroes g_cnt after consuming it (invariant: g_cnt==0 at the
// start of every kernel_launch call; zero-init at module load seeds it).
__global__ void k_scan1() {
    __shared__ int sm[SCAN_B];
    int tid = threadIdx.x;
    int g = blockIdx.x * SCAN_B + tid;
    int v = (g < NN) ? g_cnt[g] : 0;
    if (g < NN) g_cnt[g] = 0;
    sm[tid] = v;
    __syncthreads();
#pragma unroll
    for (int ofs = 1; ofs < SCAN_B; ofs <<= 1) {
        int t = (tid >= ofs) ? sm[tid - ofs] : 0;
        __syncthreads();
        sm[tid] += t;
        __syncthreads();
    }
    if (g < NN) g_off[g] = sm[tid] - v;     // exclusive within block
    if (tid == SCAN_B - 1) g_part[blockIdx.x] = sm[tid];
}

// scan3 with the partial-scan folded in: every block redundantly scans the
// 49 block partials in smem (cheap), then applies its own offset.
__global__ void k_scan3() {
    __shared__ int sm[64], orig[64];
    int tid = threadIdx.x;
    if (tid < 64) {
        int v = (tid < SCAN_NB) ? g_part[tid] : 0;
        sm[tid] = v;
        orig[tid] = v;
    }
    __syncthreads();
#pragma unroll
    for (int o = 1; o < 64; o <<= 1) {
        int t = (tid < 64 && tid >= o) ? sm[tid - o] : 0;
        __syncthreads();
        if (tid < 64) sm[tid] += t;
        __syncthreads();
    }
    int blockoff = sm[blockIdx.x] - orig[blockIdx.x];   // exclusive prefix
    int g = blockIdx.x * SCAN_B + tid;
    if (g < NN) {
        int o = g_off[g] + blockoff;
        g_off[g] = o;
        g_cur[g] = o;
    }
    if (g == 0) g_off[NN] = EE;
}

// int2-vectorized fill: 2 edges per thread
__global__ void k_fill(const int* __restrict__ ei) {
    int i = blockIdx.x * blockDim.x + threadIdx.x;
    if (i < EE / 2) {
        int2 s = ((const int2*)ei)[i];
        int2 d = ((const int2*)(ei + EE))[i];
        g_csr[atomicAdd(&g_cur[d.x], 1)] = s.x;
        g_csr[atomicAdd(&g_cur[d.y], 1)] = s.y;
    }
}

// ---------------- tiled GEMM (packed f32x2 math) ----------------------------
// H[n,CO] = X[n,K] @ W[K,CO]. Epilogue computes per-node attention scalars
// via smem cross-column reduction + direct store (no atomics, no zero-init).
// Optional fused relu(x + bias) on the X-tile load (layer-2 input).
template <int K, int CO, int TM, int TCOLS, int TROWS, bool FUSE>
__global__ void k_gemm_t(const float* __restrict__ X, const float* __restrict__ W,
                         const float* __restrict__ bias,
                         const float* __restrict__ asrc, const float* __restrict__ adst,
                         float* __restrict__ oas, float* __restrict__ oad,
                         float* __restrict__ H, int n) {
    constexpr int KT = 32;
    constexpr int THREADS = TCOLS * TROWS;
    constexpr int RPT = TM / TROWS;
    __shared__ float Xs[TM][KT];
    __shared__ __align__(16) float Ws[KT][CO];
    __shared__ float Ps[TM][TCOLS];
    __shared__ float Pd[TM][TCOLS];

    const int tid  = threadIdx.x;
    const int tcol = tid % TCOLS;
    const int trow = tid / TCOLS;
    const int row0 = blockIdx.x * TM;

    unsigned long long accA[RPT], accB[RPT];   // cols (4c,4c+1) and (4c+2,4c+3)
#pragma unroll
    for (int i = 0; i < RPT; i++) { accA[i] = 0ull; accB[i] = 0ull; }

    for (int kt = 0; kt < K; kt += KT) {
        for (int idx = tid; idx < TM * (KT / 4); idx += THREADS) {
            int r  = idx / (KT / 4);
            int c4 = idx % (KT / 4);
            int grow = row0 + r;
            float4 v = make_float4(0.f, 0.f, 0.f, 0.f);
            if (grow < n) {
                v = *(const float4*)(X + (size_t)grow * K + kt + c4 * 4);
                if constexpr (FUSE) {
                    const float* bb = bias + kt + c4 * 4;
                    v.x = fmaxf(v.x + bb[0], 0.f);
                    v.y = fmaxf(v.y + bb[1], 0.f);
                    v.z = fmaxf(v.z + bb[2], 0.f);
                    v.w = fmaxf(v.w + bb[3], 0.f);
                }
            }
            *(float4*)&Xs[r][c4 * 4] = v;
        }
        for (int idx = tid; idx < KT * (CO / 4); idx += THREADS) {
            int r  = idx / (CO / 4);
            int c4 = idx % (CO / 4);
            *(float4*)&Ws[r][c4 * 4] =
                *(const float4*)(W + (size_t)(kt + r) * CO + c4 * 4);
        }
        __syncthreads();

#pragma unroll
        for (int k4 = 0; k4 < KT; k4 += 4) {
            float4 xs[RPT];
#pragma unroll
            for (int i = 0; i < RPT; i++)
                xs[i] = *(float4*)&Xs[trow * RPT + i][k4];
#pragma unroll
            for (int kk = 0; kk < 4; kk++) {
                const unsigned long long* wp =
                    (const unsigned long long*)&Ws[k4 + kk][tcol * 4];
                unsigned long long w01 = wp[0];
                unsigned long long w23 = wp[1];
#pragma unroll
                for (int i = 0; i < RPT; i++) {
                    float xv = (kk == 0) ? xs[i].x : (kk == 1) ? xs[i].y
                             : (kk == 2) ? xs[i].z : xs[i].w;
                    unsigned long long xp = pk2(xv);
                    ffma2(accA[i], xp, w01);
                    ffma2(accB[i], xp, w23);
                }
            }
        }
        __syncthreads();
    }

    // ---- epilogue: store H; attention scalars via smem reduction ----
    float4 vs = *(const float4*)(asrc + tcol * 4);
    float4 vd = *(const float4*)(adst + tcol * 4);
#pragma unroll
    for (int i = 0; i < RPT; i++) {
        int r = trow * RPT + i;
        int grow = row0 + r;
        float2 a01 = upk2(accA[i]);
        float2 a23 = upk2(accB[i]);
        float4 acc = make_float4(a01.x, a01.y, a23.x, a23.y);
        if (grow < n)
            *(float4*)(H + (size_t)grow * CO + tcol * 4) = acc;
        Ps[r][tcol] = acc.x * vs.x + acc.y * vs.y + acc.z * vs.z + acc.w * vs.w;
        Pd[r][tcol] = acc.x * vd.x + acc.y * vd.y + acc.z * vd.z + acc.w * vd.w;
    }
    __syncthreads();
    for (int r = tid; r < TM; r += THREADS) {
        int grow = row0 + r;
        if (grow < n) {
            float ss = 0.f, sd = 0.f;
#pragma unroll
            for (int c = 0; c < TCOLS; c++) { ss += Ps[r][c]; sd += Pd[r][c]; }
            oas[grow] = ss;
            oad[grow] = sd;
        }
    }
}

// ---------------- CSR gather aggregation: one warp per dst node --------------
// (w, src) staged through per-warp smem per 32-edge batch; consume loop is
// unrolled with LDS-broadcast reads. fp32 features (fp16 ruled out: R6/R14).
// out[node] = (w_self*h[node] + sum_e w_e*h[src_e]) / (w_self + sum_e w_e)
// FINAL: fuse bias + log_softmax and write the final output row.
template <int C, bool FINAL>
__global__ void k_agg_csr(const float* __restrict__ h,
                          const float* __restrict__ as,
                          const float* __restrict__ ad,
                          const float* __restrict__ bias,
                          float* __restrict__ aggout) {
    constexpr int CPL = (C + 31) / 32;   // channels per lane
    __shared__ float sw[8][32];
    __shared__ int   ssrc[8][32];
    int wid  = threadIdx.x >> 5;
    int node = blockIdx.x * (blockDim.x >> 5) + wid;
    int lane = threadIdx.x & 31;
    if (node >= NN) return;

    float ad_n = ad[node];
    float vself = as[node] + ad_n;
    vself = (vself > 0.f) ? vself : SLOPE * vself;
    float wself = __expf(vself);

    float acc[CPL];
#pragma unroll
    for (int j = 0; j < CPL; j++) {
        int c = lane + 32 * j;
        acc[j] = (c < C) ? wself * h[(size_t)node * C + c] : 0.f;
    }

    int beg = g_off[node];
    int end = g_off[node + 1];
    float sloc = 0.f;

    for (int base = beg; base < end; base += 32) {
        int e = base + lane;
        bool valid = e < end;
        int src = valid ? g_csr[e] : 0;
        float w = 0.f;
        if (valid) {
            float v = as[src] + ad_n;
            v = (v > 0.f) ? v : SLOPE * v;
            w = __expf(v);
        }
        sloc += w;
        sw[wid][lane]   = w;
        ssrc[wid][lane] = src;
        __syncwarp();
        int cnt = min(32, end - base);
#pragma unroll 4
        for (int k = 0; k < cnt; k++) {
            float wk = sw[wid][k];
            int   sk = ssrc[wid][k];
            const float* hr = h + (size_t)sk * C;
#pragma unroll
            for (int j = 0; j < CPL; j++) {
                int c = lane + 32 * j;
                if (c < C) acc[j] += wk * hr[c];
            }
        }
        __syncwarp();
    }

#pragma unroll
    for (int o = 16; o; o >>= 1) sloc += __shfl_xor_sync(0xffffffffu, sloc, o);
    float inv = 1.f / (sloc + wself);

    if constexpr (!FINAL) {
#pragma unroll
        for (int j = 0; j < CPL; j++) {
            int c = lane + 32 * j;
            if (c < C) aggout[(size_t)node * C + c] = acc[j] * inv;
        }
    } else {
        float z[CPL];
        float mx = -3.4e38f;
#pragma unroll
        for (int j = 0; j < CPL; j++) {
            int c = lane + 32 * j;
            z[j] = (c < C) ? (acc[j] * inv + bias[c]) : -3.4e38f;
            mx = fmaxf(mx, z[j]);
        }
#pragma unroll
        for (int o = 16; o; o >>= 1) mx = fmaxf(mx, __shfl_xor_sync(0xffffffffu, mx, o));
        float sm = 0.f;
#pragma unroll
        for (int j = 0; j < CPL; j++) {
            int c = lane + 32 * j;
            if (c < C) sm += __expf(z[j] - mx);
        }
#pragma unroll
        for (int o = 16; o; o >>= 1) sm += __shfl_xor_sync(0xffffffffu, sm, o);
        float lse = mx + __logf(sm);
#pragma unroll
        for (int j = 0; j < CPL; j++) {
            int c = lane + 32 * j;
            if (c < C) aggout[(size_t)node * C + c] = z[j] - lse;
        }
    }
}

// ---------------- launch -----------------------------------------------------
static inline int cdiv(long long a, int b) { return (int)((a + b - 1) / b); }

extern "C" void kernel_launch(void* const* d_in, const int* in_sizes, int n_in,
                              void* d_out, int out_size) {
    const float* x    = (const float*)d_in[0];
    const int*   ei   = (const int*)d_in[1];   // int32 (JAX x64 disabled)
    // d_in[2] = new_edge_indexs — unused by the reference
    const float* W1   = (const float*)d_in[3];
    const float* asr1 = (const float*)d_in[4];
    const float* ads1 = (const float*)d_in[5];
    const float* b1   = (const float*)d_in[6];
    const float* W2   = (const float*)d_in[7];
    const float* asr2 = (const float*)d_in[8];
    const float* ads2 = (const float*)d_in[9];
    const float* b2   = (const float*)d_in[10];
    float* out = (float*)d_out;

    float *h1, *h2, *agg1, *as1, *ad1, *as2, *ad2;
    cudaGetSymbolAddress((void**)&h1, g_h1);
    cudaGetSymbolAddress((void**)&h2, g_h2);
    cudaGetSymbolAddress((void**)&agg1, g_agg1);
    cudaGetSymbolAddress((void**)&as1, g_as1);
    cudaGetSymbolAddress((void**)&ad1, g_ad1);
    cudaGetSymbolAddress((void**)&as2, g_as2);
    cudaGetSymbolAddress((void**)&ad2, g_ad2);

    // one-time side stream + events (host resources only; identical GPU work
    // per call, captured via the standard fork/join event pattern)
    static cudaStream_t s2 = nullptr;
    static cudaEvent_t evFork = nullptr, evJoin = nullptr;
    if (!s2) {
        cudaStreamCreateWithFlags(&s2, cudaStreamNonBlocking);
        cudaEventCreateWithFlags(&evFork, cudaEventDisableTiming);
        cudaEventCreateWithFlags(&evJoin, cudaEventDisableTiming);
    }

    const int T = 256;

    // ---- fork immediately: CSR build runs beside GEMM1 ----------------------
    cudaEventRecord(evFork, 0);
    cudaStreamWaitEvent(s2, evFork, 0);

    // side stream: CSR build (g_cnt zero by invariant; scan1 re-zeroes it)
    k_hist<<<cdiv(EE / 2, T), T, 0, s2>>>(ei);
    k_scan1<<<SCAN_NB, SCAN_B, 0, s2>>>();
    k_scan3<<<SCAN_NB, SCAN_B, 0, s2>>>();
    k_fill<<<cdiv(EE / 2, T), T, 0, s2>>>(ei);
    cudaEventRecord(evJoin, s2);

    // main stream: GEMM1 starts at t=0 (384 thr, RPT=4)
    k_gemm_t<INC, HID, 64, 24, 16, false>
        <<<cdiv(NN, 64), 24 * 16>>>(x, W1, nullptr, asr1, ads1, as1, ad1, h1, NN);

    // join: aggregation needs both GEMM1 (main) and CSR (s2)
    cudaStreamWaitEvent(0, evJoin, 0);
    k_agg_csr<HID, false><<<cdiv(NN, 8), 256>>>(h1, as1, ad1, nullptr, agg1);

    // ---- layer 2 ----
    k_gemm_t<HID, OUTC, 128, 10, 16, true>
        <<<cdiv(NN, 128), 10 * 16>>>(agg1, W2, b1, asr2, ads2, as2, ad2, h2, NN);
    k_agg_csr<OUTC, true><<<cdiv(NN, 8), 256>>>(h2, as2, ad2, b2, out);
}